// round 10
// baseline (speedup 1.0000x reference)
#include <cuda_runtime.h>
#include <cuda_bf16.h>
#include <cstdint>

typedef unsigned short ush;
typedef unsigned int uint32;

// ---------------- scratch (device globals; zero-initialized, no allocation) ----------------
__device__ ush g_imgh[2048 * 3 * 7056];   // image bf16 hi, planar [n][c][y*84+x]
__device__ ush g_imgl[2048 * 3 * 7056];
__device__ ush g_a1h[2048 * 400 * 32];    // conv1 out planes [n*400+p][32]
__device__ ush g_a1l[2048 * 400 * 32];
__device__ ush g_a2h[2048 * 81 * 64];     // conv2 out planes
__device__ ush g_a2l[2048 * 81 * 64];
__device__ ush g_a3h[2048 * 49 * 64];     // conv3 out planes [n*49+p][64] (k=p*64+c)
__device__ ush g_a3l[2048 * 49 * 64];
__device__ ush g_hidh[2048 * 8256];       // hidden planes [map 8192 | pos 64]
__device__ ush g_hidl[2048 * 8256];
__device__ float g_h[2048 * 512];         // CNN feature (fp32, feeds wfeat)
__device__ float g_wfeat[2048 * 32];
__device__ float g_part[2 * 2048 * 512];  // split-K partials (FC: 2x2048x512; policy: 8x2048x128)
__device__ float g_z[2048 * 128];
__device__ float g_bcat[128];
// pre-split, pre-swizzled bf16 weight tiles. NT=64 tile: 16KB [hi 8K][lo 8K]; NT=32: 8KB.
__device__ uint4 g_w1sw[3 * 512];         // conv1: 3 chunks x 8KB
__device__ uint4 g_w2sw[8 * 1024];        // conv2: 8 chunks x 16KB
__device__ uint4 g_w3sw[9 * 1024];        // conv3: 9 chunks
__device__ uint4 g_wfcsw[8 * 49 * 1024];  // FC: 8 ntiles x 49 chunks
__device__ uint4 g_wposw[2 * 129 * 1024]; // policy: 2 ntiles x 129 chunks

// ---------------- helpers ----------------
static __device__ __forceinline__ uint32 s2u(const void* p) {
    uint32 a;
    asm("{ .reg .u64 t; cvta.to.shared.u64 t, %1; cvt.u32.u64 %0, t; }" : "=r"(a) : "l"(p));
    return a;
}
static __device__ __forceinline__ void cpa16(uint32 d, const void* s) {
    asm volatile("cp.async.cg.shared.global [%0], [%1], 16;" :: "r"(d), "l"(s));
}
static __device__ __forceinline__ void cpa8(uint32 d, const void* s) {
    asm volatile("cp.async.ca.shared.global [%0], [%1], 8;" :: "r"(d), "l"(s));
}
static __device__ __forceinline__ void ldsm4(uint32 addr, uint32* r) {
    asm volatile("ldmatrix.sync.aligned.m8n8.x4.shared.b16 {%0,%1,%2,%3}, [%4];"
                 : "=r"(r[0]), "=r"(r[1]), "=r"(r[2]), "=r"(r[3]) : "r"(addr));
}
static __device__ __forceinline__ void ldsm2(uint32 addr, uint32* r) {
    asm volatile("ldmatrix.sync.aligned.m8n8.x2.shared.b16 {%0,%1}, [%2];"
                 : "=r"(r[0]), "=r"(r[1]) : "r"(addr));
}
static __device__ __forceinline__ void mma16816(float* c, const uint32* a, const uint32* b) {
    asm volatile(
        "mma.sync.aligned.m16n8k16.row.col.f32.bf16.bf16.f32 "
        "{%0,%1,%2,%3}, {%4,%5,%6,%7}, {%8,%9}, {%0,%1,%2,%3};"
        : "+f"(c[0]), "+f"(c[1]), "+f"(c[2]), "+f"(c[3])
        : "r"(a[0]), "r"(a[1]), "r"(a[2]), "r"(a[3]), "r"(b[0]), "r"(b[1]));
}
static __device__ __forceinline__ uint32 packsplit(float x0, float x1, uint32& lo) {
    __nv_bfloat16 h0 = __float2bfloat16_rn(x0), h1 = __float2bfloat16_rn(x1);
    __nv_bfloat16 l0 = __float2bfloat16_rn(x0 - __bfloat162float(h0));
    __nv_bfloat16 l1 = __float2bfloat16_rn(x1 - __bfloat162float(h1));
    lo = (uint32)__bfloat16_as_ushort(l0) | ((uint32)__bfloat16_as_ushort(l1) << 16);
    return (uint32)__bfloat16_as_ushort(h0) | ((uint32)__bfloat16_as_ushort(h1) << 16);
}

// ---------------- prep: weight split + swizzle into tiles ----------------
static __device__ __forceinline__ void wstore(uint4* tiles, int tilebytes, int tile,
                                              int nn, int kk, float v) {
    __nv_bfloat16 h = __float2bfloat16_rn(v);
    __nv_bfloat16 l = __float2bfloat16_rn(v - __bfloat162float(h));
    char* base = (char*)tiles + (size_t)tile * tilebytes;
    unsigned off = (unsigned)(nn * 128 + (((kk >> 3) ^ (nn & 7)) << 4) + (kk & 7) * 2);
    *(__nv_bfloat16*)(base + off) = h;
    *(__nv_bfloat16*)(base + tilebytes / 2 + off) = l;
}

__global__ void prep_kernel(const float* __restrict__ w1, const float* __restrict__ w2,
                            const float* __restrict__ w3, const float* __restrict__ wpo1,
                            const float* __restrict__ wv1, const float* __restrict__ wfc,
                            const float* __restrict__ bpo1, const float* __restrict__ bv1) {
    int i = blockIdx.x * blockDim.x + threadIdx.x;
    if (i < 6144) {  // conv1: w1[oc][c][ky][kx], k = c*64 + (ky*8+kx)  (channel-major)
        int oc = i / 192, r = i - oc * 192;            // r = c*64 + ks
        wstore(g_w1sw, 8192, r >> 6, oc, r & 63, w1[i]);
    }
    if (i < 32768) { // conv2: w2[oc][c][ky][kx], k=(ky*4+kx)*32+c
        int oc = i >> 9, c = (i >> 4) & 31, ks = i & 15;
        int k = ks * 32 + c;
        wstore(g_w2sw, 16384, k >> 6, oc, k & 63, w2[i]);
    }
    if (i < 36864) { // conv3: k=(ky*3+kx)*64+c
        int oc = i / 576, r = i - oc * 576, c = r / 9, ks = r - c * 9;
        int k = ks * 64 + c;
        wstore(g_w3sw, 16384, k >> 6, oc, k & 63, w3[i]);
    }
    if (i < 8256 * 128) { // policy/value concat
        int k = i >> 7, n = i & 127;
        float v = (n < 64) ? wpo1[k * 64 + n] : wv1[k * 64 + n - 64];
        wstore(g_wposw, 16384, (n >> 6) * 129 + (k >> 6), n & 63, k & 63, v);
    }
    if (i < 3136 * 512) { // FC: k=p*64+c; src wfc[(c*49+p)][n]
        int k = i >> 9, n = i & 511;
        int p = k >> 6, c = k & 63;
        float v = wfc[(size_t)(c * 49 + p) * 512 + n];
        wstore(g_wfcsw, 16384, (n >> 6) * 49 + p, n & 63, c, v);
    }
    if (i < 128) g_bcat[i] = (i < 64) ? bpo1[i] : bv1[i - 64];
}

// ---------------- image -> planar bf16 hi/lo (fused /255) ----------------
__global__ void imgprep_kernel(const float* __restrict__ img) {
    size_t i = (size_t)blockIdx.x * 256 + threadIdx.x;   // pixel index
    if (i >= (size_t)2048 * 7056) return;
    size_t n = i / 7056, pix = i - n * 7056;
    const float* p = img + i * 3;
#pragma unroll
    for (int c = 0; c < 3; ++c) {
        float v = p[c] * (1.f / 255.f);
        __nv_bfloat16 hb = __float2bfloat16_rn(v);
        size_t o = (n * 3 + c) * 7056 + pix;
        g_imgh[o] = __bfloat16_as_ushort(hb);
        g_imgl[o] = __bfloat16_as_ushort(__float2bfloat16_rn(v - __bfloat162float(hb)));
    }
}

// ---------------- pipelined mma.sync GEMM, bf16 hi/lo 3-MMA ----------------
// BM=128, BN=NT, BK=64 chunks. Single-sync software pipeline:
//   wait_group(0) -> syncthreads -> stage(q+1) -> compute(q)
// MODE 0: direct [gm][lda]; 1: conv2 gather; 2: conv3 gather; 3: conv1 planar (B-resident).
template<int MODE, int NT>
__global__ void __launch_bounds__(256, 2) gemmP(
    const ush* __restrict__ Ah, const ush* __restrict__ Al, int lda,
    const uint4* __restrict__ Bt, int qtotal, int qsplit,
    float* __restrict__ Cf, ush* __restrict__ Ch, ush* __restrict__ Cl,
    int ldc, int Mtotal, const float* __restrict__ bias, int dorelu)
{
    constexpr bool BRES = (MODE == 3);      // all B chunks resident in smem
    constexpr int MI = (NT == 64) ? 4 : 2;
    constexpr int ABYTES = 32768;           // A hi 16K + A lo 16K
    constexpr int BBYTES = NT * 256;        // B hi + lo per chunk
    constexpr int BUFSZ = ABYTES + (BRES ? 0 : BBYTES);
    extern __shared__ __align__(16) char smem[];
    const uint32 sb = s2u(smem);
    const uint32 Bres = sb + 2 * BUFSZ;     // B-resident region (MODE 3 only)
    const int tid = threadIdx.x;
    const int mtile = blockIdx.y, ntile = blockIdx.x, z = blockIdx.z;
    if (Cf) Cf += (size_t)z * Mtotal * ldc;

    // A gather mapping: thread = (row, half-of-64B)
    const int arow = tid & 127, ahalf = tid >> 7;
    const int gm = mtile * 128 + arow;
    size_t abase = 0; int oy = 0, ox = 0;
    if (MODE == 0) abase = (size_t)gm * lda;
    else if (MODE == 1) { int n = gm / 81, p = gm - n * 81; oy = (p / 9) * 2; ox = (p % 9) * 2; abase = (size_t)n * 12800; }
    else if (MODE == 2) { int n = gm / 49, p = gm - n * 49; oy = p / 7; ox = p - oy * 7; abase = (size_t)n * 5184; }
    else { int n = gm / 400, p = gm - n * 400; oy = p / 20; ox = p - oy * 20; abase = (size_t)n * 21168; }

    const int qb = z * qsplit;
    const int qe = min(qtotal, qb + qsplit);

    auto stage = [&](int q, int buf) {
        uint32 Ab = sb + buf * BUFSZ;
        uint32 rowb = Ab + arow * 128;
        if (MODE == 3) {
            // planar: q = channel; 4 ky rows of 8 pixels each (16B), 8B-aligned src
            size_t base = abase + (size_t)q * 7056 + (size_t)(oy * 4) * 84 + ox * 4;
#pragma unroll
            for (int i = 0; i < 4; ++i) {
                int ky = ahalf * 4 + i;
                const char* gh = (const char*)(Ah + base + ky * 84);
                const char* gl = (const char*)(Al + base + ky * 84);
                uint32 d = rowb + ((ky ^ (arow & 7)) << 4);
                cpa8(d, gh); cpa8(d + 8, gh + 8);
                cpa8(d + 16384, gl); cpa8(d + 16384 + 8, gl + 8);
            }
        } else {
            size_t off;
            if (MODE == 0) off = abase + (size_t)q * 64 + ahalf * 32;
            else if (MODE == 1) {
                int ks = q * 2 + ahalf;
                off = abase + (size_t)((oy + (ks >> 2)) * 20 + ox + (ks & 3)) * 32;
            } else {
                int ky = q / 3, kx = q - ky * 3;
                off = abase + (size_t)((oy + ky) * 9 + ox + kx) * 64 + ahalf * 32;
            }
            const char* gh = (const char*)(Ah + off);
            const char* gl = (const char*)(Al + off);
#pragma unroll
            for (int i = 0; i < 4; ++i) {
                int seg = ahalf * 4 + i;
                uint32 d = rowb + ((seg ^ (arow & 7)) << 4);
                cpa16(d, gh + i * 16);
                cpa16(d + 16384, gl + i * 16);
            }
        }
        if (!BRES) {
            uint32 Bb = Ab + ABYTES;
            const uint4* bt = Bt + (size_t)(ntile * qtotal + q) * (BBYTES / 16);
#pragma unroll
            for (int i = 0; i < BBYTES / 16 / 256; ++i)
                cpa16(Bb + (tid + i * 256) * 16, bt + tid + i * 256);
        }
        asm volatile("cp.async.commit_group;" ::: "memory");
    };

    const int wid = tid >> 5, L = tid & 31;
    const int warpM = (NT == 64) ? (wid & 1) * 64 : (wid & 3) * 32;
    const int warpN = (NT == 64) ? (wid >> 1) * 16 : (wid >> 2) * 16;
    const int arow0 = warpM + (L & 7) + ((L >> 3) & 1) * 8;
    const int asegh = (L >> 4) & 1;
    const int brow0 = warpN + (L & 7);
    const int bsegh = (L >> 3) & 1;

    float acc[MI][2][4];
#pragma unroll
    for (int mi = 0; mi < MI; ++mi)
#pragma unroll
        for (int ni = 0; ni < 2; ++ni)
#pragma unroll
            for (int r = 0; r < 4; ++r) acc[mi][ni][r] = 0.f;

    // prologue: (optional) resident B + first A chunk, one commit group
    if (BRES) {
        const uint4* bt = Bt + (size_t)(ntile * qtotal + qb) * (BBYTES / 16);
        const int total = (qe - qb) * (BBYTES / 16);
        for (int i = tid; i < total; i += 256) cpa16(Bres + i * 16, bt + i);
    }
    stage(qb, 0);

    for (int q = qb; q < qe; ++q) {
        int cb = (q - qb) & 1;
        asm volatile("cp.async.wait_group 0;" ::: "memory");
        __syncthreads();
        if (q + 1 < qe) stage(q + 1, cb ^ 1);
        uint32 Ab = sb + cb * BUFSZ;
        uint32 Bb = BRES ? (Bres + (q - qb) * BBYTES) : (Ab + ABYTES);
#pragma unroll
        for (int ks4 = 0; ks4 < 4; ++ks4) {
            uint32 ah[MI][4], al[MI][4], bh[2][2], bl[2][2];
#pragma unroll
            for (int mi = 0; mi < MI; ++mi) {
                int row = arow0 + mi * 16;
                int seg = ks4 * 2 + asegh;
                uint32 ad = Ab + row * 128 + ((seg ^ (row & 7)) << 4);
                ldsm4(ad, ah[mi]);
                ldsm4(ad + 16384, al[mi]);
            }
#pragma unroll
            for (int ni = 0; ni < 2; ++ni) {
                int row = brow0 + ni * 8;
                int seg = ks4 * 2 + bsegh;
                uint32 bd = Bb + row * 128 + ((seg ^ (row & 7)) << 4);
                ldsm2(bd, bh[ni]);
                ldsm2(bd + NT * 128, bl[ni]);
            }
#pragma unroll
            for (int mi = 0; mi < MI; ++mi)
#pragma unroll
                for (int ni = 0; ni < 2; ++ni) {
                    mma16816(acc[mi][ni], ah[mi], bh[ni]);
                    mma16816(acc[mi][ni], ah[mi], bl[ni]);
                    mma16816(acc[mi][ni], al[mi], bh[ni]);
                }
        }
    }

    // ---- epilogue ----
    const int gID = L >> 2, tg = L & 3;
#pragma unroll
    for (int mi = 0; mi < MI; ++mi)
#pragma unroll
        for (int ni = 0; ni < 2; ++ni) {
            int m = mtile * 128 + warpM + mi * 16 + gID;
            int col = ntile * NT + warpN + ni * 8 + tg * 2;
            float x0 = acc[mi][ni][0], x1 = acc[mi][ni][1];
            float x2 = acc[mi][ni][2], x3 = acc[mi][ni][3];
            if (bias) {
                float2 bb = *(const float2*)(bias + col);
                x0 += bb.x; x1 += bb.y; x2 += bb.x; x3 += bb.y;
            }
            if (dorelu) {
                x0 = fmaxf(x0, 0.f); x1 = fmaxf(x1, 0.f);
                x2 = fmaxf(x2, 0.f); x3 = fmaxf(x3, 0.f);
            }
            if (Cf) {
                *(float2*)(Cf + (size_t)m * ldc + col) = make_float2(x0, x1);
                *(float2*)(Cf + (size_t)(m + 8) * ldc + col) = make_float2(x2, x3);
            } else {
                uint32 lo, hi;
                hi = packsplit(x0, x1, lo);
                *(uint32*)(Ch + (size_t)m * ldc + col) = hi;
                *(uint32*)(Cl + (size_t)m * ldc + col) = lo;
                hi = packsplit(x2, x3, lo);
                *(uint32*)(Ch + (size_t)(m + 8) * ldc + col) = hi;
                *(uint32*)(Cl + (size_t)(m + 8) * ldc + col) = lo;
            }
        }
}

// ---------------- split-K reduce + bias + relu ----------------
__global__ void reduce_kernel(const float* __restrict__ bias, float* __restrict__ outp,
                              int N, int nparts, int stride, int count, int dorelu) {
    int i = blockIdx.x * blockDim.x + threadIdx.x;
    if (i >= count) return;
    float s = 0.f;
    for (int ss = 0; ss < nparts; ++ss) s += g_part[(size_t)ss * stride + i];
    s += bias[i % N];
    outp[i] = dorelu ? fmaxf(s, 0.f) : s;
}

// ---------------- wfeat = g_h @ Ww + bw ----------------
__global__ void __launch_bounds__(256) wfeat_kernel(const float* __restrict__ Ww,
                                                    const float* __restrict__ bw) {
    int t = blockIdx.x * 256 + threadIdx.x;
    int n = t >> 5, oc = t & 31;
    const float* hrow = g_h + (size_t)n * 512;
    float s = bw[oc];
#pragma unroll 8
    for (int k = 0; k < 512; ++k) s += hrow[k] * Ww[k * 32 + oc];
    g_wfeat[t] = s;
}

// ---------------- sequential scan: writes hidden planes + fp32 state ----------------
__global__ void __launch_bounds__(256) scan_kernel(const float* __restrict__ done,
                                                   const float* __restrict__ state0,
                                                   const int* __restrict__ position,
                                                   float* __restrict__ out_state) {
    const int b = blockIdx.x, cq = blockIdx.y * 8, j = threadIdx.x;
    float st[8];
#pragma unroll
    for (int c = 0; c < 8; ++c) st[c] = state0[b * 8192 + (cq + c) * 256 + j];
    for (int t = 0; t < 32; ++t) {
        int idx = t * 64 + b;
        float m = 1.0f - done[idx];
#pragma unroll
        for (int c = 0; c < 8; ++c) st[c] *= m;
        int p0 = position[idx * 2], p1 = position[idx * 2 + 1];
        if (j == p0 * 16 + p1) {
#pragma unroll
            for (int c = 0; c < 8; ++c) st[c] += g_wfeat[idx * 32 + cq + c];
        }
        size_t rb = (size_t)idx * 8256;
#pragma unroll
        for (int c = 0; c < 8; ++c) {
            __nv_bfloat16 h = __float2bfloat16_rn(st[c]);
            g_hidh[rb + (cq + c) * 256 + j] = __bfloat16_as_ushort(h);
            g_hidl[rb + (cq + c) * 256 + j] =
                __bfloat16_as_ushort(__float2bfloat16_rn(st[c] - __bfloat162float(h)));
        }
    }
#pragma unroll
    for (int c = 0; c < 8; ++c) out_state[b * 8192 + (cq + c) * 256 + j] = st[c];
}

// ---------------- pos_net -> hidden plane cols 8192..8255 ----------------
__global__ void __launch_bounds__(64) posnet_kernel(const int* __restrict__ position,
                                                    const float* __restrict__ wp1,
                                                    const float* __restrict__ bp1,
                                                    const float* __restrict__ wp2,
                                                    const float* __restrict__ bp2) {
    __shared__ float hr[64];
    const int n = blockIdx.x, k = threadIdx.x;
    int p0 = position[n * 2], p1 = position[n * 2 + 1];
    hr[k] = fmaxf(wp1[p0 * 64 + k] + wp1[(16 + p1) * 64 + k] + bp1[k], 0.f);
    __syncthreads();
    float s = bp2[k];
#pragma unroll 8
    for (int j = 0; j < 64; ++j) s += hr[j] * wp2[j * 64 + k];
    __nv_bfloat16 h = __float2bfloat16_rn(s);
    g_hidh[(size_t)n * 8256 + 8192 + k] = __bfloat16_as_ushort(h);
    g_hidl[(size_t)n * 8256 + 8192 + k] =
        __bfloat16_as_ushort(__float2bfloat16_rn(s - __bfloat162float(h)));
}

// ---------------- heads ----------------
__global__ void heads_kernel(const float* __restrict__ wpo2, const float* __restrict__ bpo2,
                             const float* __restrict__ wv2, const float* __restrict__ bv2,
                             float* __restrict__ out_logits, float* __restrict__ out_v) {
    int n = blockIdx.x * blockDim.x + threadIdx.x;
    if (n >= 2048) return;
    const float* z = g_z + (size_t)n * 128;
    float lg[5];
#pragma unroll
    for (int a = 0; a < 5; ++a) lg[a] = bpo2[a];
    float vv = bv2[0];
#pragma unroll 4
    for (int j = 0; j < 64; ++j) {
        float zj = z[j];
#pragma unroll
        for (int a = 0; a < 5; ++a) lg[a] += zj * wpo2[j * 5 + a];
        vv += z[64 + j] * wv2[j];
    }
#pragma unroll
    for (int a = 0; a < 5; ++a) out_logits[n * 5 + a] = lg[a];
    out_v[n] = vv;
}

// ---------------- launch ----------------
extern "C" void kernel_launch(void* const* d_in, const int* in_sizes, int n_in,
                              void* d_out, int out_size) {
    bool dict_order = (in_sizes[3] == 4096 && in_sizes[4] == 6144);
    int wb = dict_order ? 4 : 3;
    int posIdx = dict_order ? 3 : 25;

    const float* image  = (const float*)d_in[0];
    const float* done   = (const float*)d_in[1];
    const float* state0 = (const float*)d_in[2];
    const int*   position = (const int*)d_in[posIdx];
    const float* w1  = (const float*)d_in[wb + 0];
    const float* b1  = (const float*)d_in[wb + 1];
    const float* w2  = (const float*)d_in[wb + 2];
    const float* b2  = (const float*)d_in[wb + 3];
    const float* w3  = (const float*)d_in[wb + 4];
    const float* b3  = (const float*)d_in[wb + 5];
    const float* wfc = (const float*)d_in[wb + 6];
    const float* bfc = (const float*)d_in[wb + 7];
    const float* Ww  = (const float*)d_in[wb + 8];
    const float* bw  = (const float*)d_in[wb + 9];
    const float* wp1 = (const float*)d_in[wb + 10];
    const float* bp1 = (const float*)d_in[wb + 11];
    const float* wp2 = (const float*)d_in[wb + 12];
    const float* bp2 = (const float*)d_in[wb + 13];
    const float* wpo1 = (const float*)d_in[wb + 14];
    const float* bpo1 = (const float*)d_in[wb + 15];
    const float* wpo2 = (const float*)d_in[wb + 16];
    const float* bpo2 = (const float*)d_in[wb + 17];
    const float* wv1 = (const float*)d_in[wb + 18];
    const float* bv1 = (const float*)d_in[wb + 19];
    const float* wv2 = (const float*)d_in[wb + 20];
    const float* bv2 = (const float*)d_in[wb + 21];

    float* out = (float*)d_out;
    float* out_logits = out;
    float* out_v      = out + 10240;
    float* out_state  = out + 12288;

    ush *p_imgh, *p_imgl, *p_a1h, *p_a1l, *p_a2h, *p_a2l, *p_a3h, *p_a3l, *p_hidh, *p_hidl;
    float *p_h, *p_part, *p_z, *p_bcat;
    uint4 *p_w1sw, *p_w2sw, *p_w3sw, *p_wfcsw, *p_wposw;
    cudaGetSymbolAddress((void**)&p_imgh, g_imgh);
    cudaGetSymbolAddress((void**)&p_imgl, g_imgl);
    cudaGetSymbolAddress((void**)&p_a1h, g_a1h);
    cudaGetSymbolAddress((void**)&p_a1l, g_a1l);
    cudaGetSymbolAddress((void**)&p_a2h, g_a2h);
    cudaGetSymbolAddress((void**)&p_a2l, g_a2l);
    cudaGetSymbolAddress((void**)&p_a3h, g_a3h);
    cudaGetSymbolAddress((void**)&p_a3l, g_a3l);
    cudaGetSymbolAddress((void**)&p_hidh, g_hidh);
    cudaGetSymbolAddress((void**)&p_hidl, g_hidl);
    cudaGetSymbolAddress((void**)&p_h, g_h);
    cudaGetSymbolAddress((void**)&p_part, g_part);
    cudaGetSymbolAddress((void**)&p_z, g_z);
    cudaGetSymbolAddress((void**)&p_bcat, g_bcat);
    cudaGetSymbolAddress((void**)&p_w1sw, g_w1sw);
    cudaGetSymbolAddress((void**)&p_w2sw, g_w2sw);
    cudaGetSymbolAddress((void**)&p_w3sw, g_w3sw);
    cudaGetSymbolAddress((void**)&p_wfcsw, g_wfcsw);
    cudaGetSymbolAddress((void**)&p_wposw, g_wposw);

    const int SM64 = 2 * (32768 + 64 * 256);        // 98304
    const int SM1  = 2 * 32768 + 3 * (32 * 256);    // 90112 (conv1: A dbl-buf + resident B)
    cudaFuncSetAttribute(gemmP<3,32>, cudaFuncAttributeMaxDynamicSharedMemorySize, SM1);
    cudaFuncSetAttribute(gemmP<1,64>, cudaFuncAttributeMaxDynamicSharedMemorySize, SM64);
    cudaFuncSetAttribute(gemmP<2,64>, cudaFuncAttributeMaxDynamicSharedMemorySize, SM64);
    cudaFuncSetAttribute(gemmP<0,64>, cudaFuncAttributeMaxDynamicSharedMemorySize, SM64);

    prep_kernel<<<3137, 512>>>(w1, w2, w3, wpo1, wv1, wfc, bpo1, bv1);
    imgprep_kernel<<<56448, 256>>>(image);
    // conv1: M=819200, N=32, K=192 (3 chunks, channel-planar, B-resident)
    gemmP<3,32><<<dim3(1, 6400, 1), 256, SM1>>>(p_imgh, p_imgl, 0, p_w1sw, 3, 3,
                                                (float*)0, p_a1h, p_a1l, 32, 819200, b1, 1);
    // conv2: M=165888, N=64, K=512 (8 chunks)
    gemmP<1,64><<<dim3(1, 1296, 1), 256, SM64>>>(p_a1h, p_a1l, 0, p_w2sw, 8, 8,
                                                 (float*)0, p_a2h, p_a2l, 64, 165888, b2, 1);
    // conv3: M=100352, N=64, K=576 (9 chunks)
    gemmP<2,64><<<dim3(1, 784, 1), 256, SM64>>>(p_a2h, p_a2l, 0, p_w3sw, 9, 9,
                                                (float*)0, p_a3h, p_a3l, 64, 100352, b3, 1);
    // FC: M=2048, N=512 (8 ntiles), K=3136 (49 chunks), split-K=2
    gemmP<0,64><<<dim3(8, 16, 2), 256, SM64>>>(p_a3h, p_a3l, 3136, p_wfcsw, 49, 25,
                                               p_part, (ush*)0, (ush*)0, 512, 2048,
                                               (const float*)0, 0);
    reduce_kernel<<<2048, 512>>>(bfc, p_h, 512, 2, 2048 * 512, 2048 * 512, 1);
    wfeat_kernel<<<256, 256>>>(Ww, bw);
    scan_kernel<<<dim3(64, 4, 1), 256>>>(done, state0, position, out_state);
    posnet_kernel<<<2048, 64>>>(position, wp1, bp1, wp2, bp2);
    // policy/value: M=2048, N=128 (2 ntiles), K=8256 (129 chunks), split-K=8
    gemmP<0,64><<<dim3(2, 16, 8), 256, SM64>>>(p_hidh, p_hidl, 8256, p_wposw, 129, 17,
                                               p_part, (ush*)0, (ush*)0, 128, 2048,
                                               (const float*)0, 0);
    reduce_kernel<<<512, 512>>>(p_bcat, p_z, 128, 8, 2048 * 128, 2048 * 128, 1);
    heads_kernel<<<16, 128>>>(wpo2, bpo2, wv2, bv2, out_logits, out_v);
}

// round 11
// speedup vs baseline: 1.1347x; 1.1347x over previous
#include <cuda_runtime.h>
#include <cuda_fp16.h>
#include <cstdint>

typedef unsigned short ush;
typedef unsigned int uint32;

// ---------------- scratch (device globals; zero-initialized, no allocation) ----------------
__device__ ush g_imgh[2048 * 3 * 7056];   // image fp16 hi, planar [n][c][y*84+x]
__device__ ush g_imgl[2048 * 3 * 7056];
__device__ ush g_a1h[2048 * 400 * 32];    // conv1 out planes [n*400+p][32]
__device__ ush g_a1l[2048 * 400 * 32];
__device__ ush g_a2h[2048 * 81 * 64];     // conv2 out planes
__device__ ush g_a2l[2048 * 81 * 64];
__device__ ush g_a3h[2048 * 49 * 64];     // conv3 out planes [n*49+p][64] (k=p*64+c)
__device__ ush g_a3l[2048 * 49 * 64];
__device__ ush g_hidh[2048 * 8256];       // hidden planes [map 8192 | pos 64]
__device__ ush g_hidl[2048 * 8256];
__device__ float g_h[2048 * 512];         // CNN feature (fp32, feeds wfeat)
__device__ float g_wfeat[2048 * 32];
__device__ float g_part[2 * 2048 * 512];  // split-K partials (FC: 2x2048x512; policy: 8x2048x128)
__device__ float g_z[2048 * 128];
__device__ float g_bcat[128];
// fp16 weight tiles (hi only), pre-swizzled: NT=64 tile 8KB; NT=32 tile 4KB.
__device__ uint4 g_w1sw[3 * 256];         // conv1: 3 chunks x 4KB
__device__ uint4 g_w2sw[8 * 512];         // conv2: 8 chunks x 8KB
__device__ uint4 g_w3sw[9 * 512];         // conv3: 9 chunks
__device__ uint4 g_wfcsw[8 * 49 * 512];   // FC: 8 ntiles x 49 chunks
__device__ uint4 g_wposw[2 * 129 * 512];  // policy: 2 ntiles x 129 chunks

// ---------------- helpers ----------------
static __device__ __forceinline__ uint32 s2u(const void* p) {
    uint32 a;
    asm("{ .reg .u64 t; cvta.to.shared.u64 t, %1; cvt.u32.u64 %0, t; }" : "=r"(a) : "l"(p));
    return a;
}
static __device__ __forceinline__ void cpa16(uint32 d, const void* s) {
    asm volatile("cp.async.cg.shared.global [%0], [%1], 16;" :: "r"(d), "l"(s));
}
static __device__ __forceinline__ void cpa8(uint32 d, const void* s) {
    asm volatile("cp.async.ca.shared.global [%0], [%1], 8;" :: "r"(d), "l"(s));
}
static __device__ __forceinline__ void ldsm4(uint32 addr, uint32* r) {
    asm volatile("ldmatrix.sync.aligned.m8n8.x4.shared.b16 {%0,%1,%2,%3}, [%4];"
                 : "=r"(r[0]), "=r"(r[1]), "=r"(r[2]), "=r"(r[3]) : "r"(addr));
}
static __device__ __forceinline__ void ldsm2(uint32 addr, uint32* r) {
    asm volatile("ldmatrix.sync.aligned.m8n8.x2.shared.b16 {%0,%1}, [%2];"
                 : "=r"(r[0]), "=r"(r[1]) : "r"(addr));
}
static __device__ __forceinline__ void mmaF16(float* c, const uint32* a, const uint32* b) {
    asm volatile(
        "mma.sync.aligned.m16n8k16.row.col.f32.f16.f16.f32 "
        "{%0,%1,%2,%3}, {%4,%5,%6,%7}, {%8,%9}, {%0,%1,%2,%3};"
        : "+f"(c[0]), "+f"(c[1]), "+f"(c[2]), "+f"(c[3])
        : "r"(a[0]), "r"(a[1]), "r"(a[2]), "r"(a[3]), "r"(b[0]), "r"(b[1]));
}
static __device__ __forceinline__ uint32 packsplit(float x0, float x1, uint32& lo) {
    __half h0 = __float2half_rn(x0), h1 = __float2half_rn(x1);
    __half l0 = __float2half_rn(x0 - __half2float(h0));
    __half l1 = __float2half_rn(x1 - __half2float(h1));
    lo = (uint32)__half_as_ushort(l0) | ((uint32)__half_as_ushort(l1) << 16);
    return (uint32)__half_as_ushort(h0) | ((uint32)__half_as_ushort(h1) << 16);
}

// ---------------- prep: weight fp16 quantize + swizzle into tiles ----------------
static __device__ __forceinline__ void wstore(uint4* tiles, int tilebytes, int tile,
                                              int nn, int kk, float v) {
    char* base = (char*)tiles + (size_t)tile * tilebytes;
    unsigned off = (unsigned)(nn * 128 + (((kk >> 3) ^ (nn & 7)) << 4) + (kk & 7) * 2);
    *(__half*)(base + off) = __float2half_rn(v);
}

__global__ void prep_kernel(const float* __restrict__ w1, const float* __restrict__ w2,
                            const float* __restrict__ w3, const float* __restrict__ wpo1,
                            const float* __restrict__ wv1, const float* __restrict__ wfc,
                            const float* __restrict__ bpo1, const float* __restrict__ bv1) {
    int i = blockIdx.x * blockDim.x + threadIdx.x;
    if (i < 6144) {  // conv1: w1[oc][c][ky][kx], k = c*64 + (ky*8+kx)
        int oc = i / 192, r = i - oc * 192;
        wstore(g_w1sw, 4096, r >> 6, oc, r & 63, w1[i]);
    }
    if (i < 32768) { // conv2: k=(ky*4+kx)*32+c
        int oc = i >> 9, c = (i >> 4) & 31, ks = i & 15;
        int k = ks * 32 + c;
        wstore(g_w2sw, 8192, k >> 6, oc, k & 63, w2[i]);
    }
    if (i < 36864) { // conv3: k=(ky*3+kx)*64+c
        int oc = i / 576, r = i - oc * 576, c = r / 9, ks = r - c * 9;
        int k = ks * 64 + c;
        wstore(g_w3sw, 8192, k >> 6, oc, k & 63, w3[i]);
    }
    if (i < 8256 * 128) { // policy/value concat
        int k = i >> 7, n = i & 127;
        float v = (n < 64) ? wpo1[k * 64 + n] : wv1[k * 64 + n - 64];
        wstore(g_wposw, 8192, (n >> 6) * 129 + (k >> 6), n & 63, k & 63, v);
    }
    if (i < 3136 * 512) { // FC: k=p*64+c; src wfc[(c*49+p)][n]
        int k = i >> 9, n = i & 511;
        int p = k >> 6, c = k & 63;
        float v = wfc[(size_t)(c * 49 + p) * 512 + n];
        wstore(g_wfcsw, 8192, (n >> 6) * 49 + p, n & 63, c, v);
    }
    if (i < 128) g_bcat[i] = (i < 64) ? bpo1[i] : bv1[i - 64];
}

// ---------------- image -> planar fp16 hi/lo (fused /255) ----------------
__global__ void imgprep_kernel(const float* __restrict__ img) {
    size_t i = (size_t)blockIdx.x * 256 + threadIdx.x;   // pixel index
    if (i >= (size_t)2048 * 7056) return;
    size_t n = i / 7056, pix = i - n * 7056;
    const float* p = img + i * 3;
#pragma unroll
    for (int c = 0; c < 3; ++c) {
        float v = p[c] * (1.f / 255.f);
        __half hb = __float2half_rn(v);
        size_t o = (n * 3 + c) * 7056 + pix;
        g_imgh[o] = __half_as_ushort(hb);
        g_imgl[o] = __half_as_ushort(__float2half_rn(v - __half2float(hb)));
    }
}

// ---------------- pipelined mma.sync GEMM, fp16 exact-A x fp16-B (2 MMAs) ----------------
// BM=128, BN=NT, BK=64 chunks. wait->sync->stage(q+1)->compute(q).
// MODE 0: direct [gm][lda]; 1: conv2 gather; 2: conv3 gather; 3: conv1 planar (B-resident).
template<int MODE, int NT>
__global__ void __launch_bounds__(256, 2) gemmP(
    const ush* __restrict__ Ah, const ush* __restrict__ Al, int lda,
    const uint4* __restrict__ Bt, int qtotal, int qsplit,
    float* __restrict__ Cf, ush* __restrict__ Ch, ush* __restrict__ Cl,
    int ldc, int Mtotal, const float* __restrict__ bias, int dorelu)
{
    constexpr bool BRES = (MODE == 3);
    constexpr int MI = 2;
    constexpr int NI = (NT == 64) ? 4 : 2;
    constexpr int ABYTES = 32768;           // A hi 16K + A lo 16K
    constexpr int BBYTES = NT * 128;        // B hi per chunk
    constexpr int BUFSZ = ABYTES + (BRES ? 0 : BBYTES);
    extern __shared__ __align__(16) char smem[];
    const uint32 sb = s2u(smem);
    const uint32 Bres = sb + 2 * BUFSZ;     // B-resident region (MODE 3 only)
    const int tid = threadIdx.x;
    const int mtile = blockIdx.y, ntile = blockIdx.x, z = blockIdx.z;
    if (Cf) Cf += (size_t)z * Mtotal * ldc;

    // A gather mapping: thread = (row, half-of-64B)
    const int arow = tid & 127, ahalf = tid >> 7;
    const int gm = mtile * 128 + arow;
    size_t abase = 0; int oy = 0, ox = 0;
    if (MODE == 0) abase = (size_t)gm * lda;
    else if (MODE == 1) { int n = gm / 81, p = gm - n * 81; oy = (p / 9) * 2; ox = (p % 9) * 2; abase = (size_t)n * 12800; }
    else if (MODE == 2) { int n = gm / 49, p = gm - n * 49; oy = p / 7; ox = p - oy * 7; abase = (size_t)n * 5184; }
    else { int n = gm / 400, p = gm - n * 400; oy = p / 20; ox = p - oy * 20; abase = (size_t)n * 21168; }

    const int qb = z * qsplit;
    const int qe = min(qtotal, qb + qsplit);

    auto stage = [&](int q, int buf) {
        uint32 Ab = sb + buf * BUFSZ;
        uint32 rowb = Ab + arow * 128;
        if (MODE == 3) {
            size_t base = abase + (size_t)q * 7056 + (size_t)(oy * 4) * 84 + ox * 4;
#pragma unroll
            for (int i = 0; i < 4; ++i) {
                int ky = ahalf * 4 + i;
                const char* gh = (const char*)(Ah + base + ky * 84);
                const char* gl = (const char*)(Al + base + ky * 84);
                uint32 d = rowb + ((ky ^ (arow & 7)) << 4);
                cpa8(d, gh); cpa8(d + 8, gh + 8);
                cpa8(d + 16384, gl); cpa8(d + 16384 + 8, gl + 8);
            }
        } else {
            size_t off;
            if (MODE == 0) off = abase + (size_t)q * 64 + ahalf * 32;
            else if (MODE == 1) {
                int ks = q * 2 + ahalf;
                off = abase + (size_t)((oy + (ks >> 2)) * 20 + ox + (ks & 3)) * 32;
            } else {
                int ky = q / 3, kx = q - ky * 3;
                off = abase + (size_t)((oy + ky) * 9 + ox + kx) * 64 + ahalf * 32;
            }
            const char* gh = (const char*)(Ah + off);
            const char* gl = (const char*)(Al + off);
#pragma unroll
            for (int i = 0; i < 4; ++i) {
                int seg = ahalf * 4 + i;
                uint32 d = rowb + ((seg ^ (arow & 7)) << 4);
                cpa16(d, gh + i * 16);
                cpa16(d + 16384, gl + i * 16);
            }
        }
        if (!BRES) {
            uint32 Bb = Ab + ABYTES;
            const uint4* bt = Bt + (size_t)(ntile * qtotal + q) * (BBYTES / 16);
#pragma unroll
            for (int i = 0; i < (BBYTES / 16 + 255) / 256; ++i) {
                int e = tid + i * 256;
                if (e < BBYTES / 16) cpa16(Bb + e * 16, bt + e);
            }
        }
        asm volatile("cp.async.commit_group;" ::: "memory");
    };

    // warp layout: 4M x 2N (NT=64): warp covers 32 rows x 32 cols; NT=32: 32 x 16
    const int wid = tid >> 5, L = tid & 31;
    const int warpM = (wid & 3) * 32;
    const int warpN = (wid >> 2) * (NI * 8);
    const int arow0 = warpM + (L & 7) + ((L >> 3) & 1) * 8;
    const int asegh = (L >> 4) & 1;
    const int brow0 = warpN + (L & 7);
    const int bsegh = (L >> 3) & 1;

    float acc[MI][NI][4];
#pragma unroll
    for (int mi = 0; mi < MI; ++mi)
#pragma unroll
        for (int ni = 0; ni < NI; ++ni)
#pragma unroll
            for (int r = 0; r < 4; ++r) acc[mi][ni][r] = 0.f;

    if (BRES) {
        const uint4* bt = Bt + (size_t)(ntile * qtotal + qb) * (BBYTES / 16);
        const int total = (qe - qb) * (BBYTES / 16);
        for (int i = tid; i < total; i += 256) cpa16(Bres + i * 16, bt + i);
    }
    stage(qb, 0);

    for (int q = qb; q < qe; ++q) {
        int cb = (q - qb) & 1;
        asm volatile("cp.async.wait_group 0;" ::: "memory");
        __syncthreads();
        if (q + 1 < qe) stage(q + 1, cb ^ 1);
        uint32 Ab = sb + cb * BUFSZ;
        uint32 Bb = BRES ? (Bres + (q - qb) * BBYTES) : (Ab + ABYTES);
#pragma unroll
        for (int ks4 = 0; ks4 < 4; ++ks4) {
            uint32 ah[MI][4], al[MI][4], bh[NI][2];
#pragma unroll
            for (int mi = 0; mi < MI; ++mi) {
                int row = arow0 + mi * 16;
                int seg = ks4 * 2 + asegh;
                uint32 ad = Ab + row * 128 + ((seg ^ (row & 7)) << 4);
                ldsm4(ad, ah[mi]);
                ldsm4(ad + 16384, al[mi]);
            }
#pragma unroll
            for (int ni = 0; ni < NI; ++ni) {
                int row = brow0 + ni * 8;
                int seg = ks4 * 2 + bsegh;
                uint32 bd = Bb + row * 128 + ((seg ^ (row & 7)) << 4);
                ldsm2(bd, bh[ni]);
            }
#pragma unroll
            for (int mi = 0; mi < MI; ++mi)
#pragma unroll
                for (int ni = 0; ni < NI; ++ni) {
                    mmaF16(acc[mi][ni], ah[mi], bh[ni]);
                    mmaF16(acc[mi][ni], al[mi], bh[ni]);
                }
        }
    }

    // ---- epilogue ----
    const int gID = L >> 2, tg = L & 3;
#pragma unroll
    for (int mi = 0; mi < MI; ++mi)
#pragma unroll
        for (int ni = 0; ni < NI; ++ni) {
            int m = mtile * 128 + warpM + mi * 16 + gID;
            int col = ntile * NT + warpN + ni * 8 + tg * 2;
            float x0 = acc[mi][ni][0], x1 = acc[mi][ni][1];
            float x2 = acc[mi][ni][2], x3 = acc[mi][ni][3];
            if (bias) {
                float2 bb = *(const float2*)(bias + col);
                x0 += bb.x; x1 += bb.y; x2 += bb.x; x3 += bb.y;
            }
            if (dorelu) {
                x0 = fmaxf(x0, 0.f); x1 = fmaxf(x1, 0.f);
                x2 = fmaxf(x2, 0.f); x3 = fmaxf(x3, 0.f);
            }
            if (Cf) {
                *(float2*)(Cf + (size_t)m * ldc + col) = make_float2(x0, x1);
                *(float2*)(Cf + (size_t)(m + 8) * ldc + col) = make_float2(x2, x3);
            } else {
                uint32 lo, hi;
                hi = packsplit(x0, x1, lo);
                *(uint32*)(Ch + (size_t)m * ldc + col) = hi;
                *(uint32*)(Cl + (size_t)m * ldc + col) = lo;
                hi = packsplit(x2, x3, lo);
                *(uint32*)(Ch + (size_t)(m + 8) * ldc + col) = hi;
                *(uint32*)(Cl + (size_t)(m + 8) * ldc + col) = lo;
            }
        }
}

// ---------------- split-K reduce + bias + relu ----------------
__global__ void reduce_kernel(const float* __restrict__ bias, float* __restrict__ outp,
                              int N, int nparts, int stride, int count, int dorelu) {
    int i = blockIdx.x * blockDim.x + threadIdx.x;
    if (i >= count) return;
    float s = 0.f;
    for (int ss = 0; ss < nparts; ++ss) s += g_part[(size_t)ss * stride + i];
    s += bias[i % N];
    outp[i] = dorelu ? fmaxf(s, 0.f) : s;
}

// ---------------- wfeat = g_h @ Ww + bw ----------------
__global__ void __launch_bounds__(256) wfeat_kernel(const float* __restrict__ Ww,
                                                    const float* __restrict__ bw) {
    int t = blockIdx.x * 256 + threadIdx.x;
    int n = t >> 5, oc = t & 31;
    const float* hrow = g_h + (size_t)n * 512;
    float s = bw[oc];
#pragma unroll 8
    for (int k = 0; k < 512; ++k) s += hrow[k] * Ww[k * 32 + oc];
    g_wfeat[t] = s;
}

// ---------------- sequential scan: writes hidden planes + fp32 state ----------------
__global__ void __launch_bounds__(256) scan_kernel(const float* __restrict__ done,
                                                   const float* __restrict__ state0,
                                                   const int* __restrict__ position,
                                                   float* __restrict__ out_state) {
    const int b = blockIdx.x, cq = blockIdx.y * 8, j = threadIdx.x;
    float st[8];
#pragma unroll
    for (int c = 0; c < 8; ++c) st[c] = state0[b * 8192 + (cq + c) * 256 + j];
    for (int t = 0; t < 32; ++t) {
        int idx = t * 64 + b;
        float m = 1.0f - done[idx];
#pragma unroll
        for (int c = 0; c < 8; ++c) st[c] *= m;
        int p0 = position[idx * 2], p1 = position[idx * 2 + 1];
        if (j == p0 * 16 + p1) {
#pragma unroll
            for (int c = 0; c < 8; ++c) st[c] += g_wfeat[idx * 32 + cq + c];
        }
        size_t rb = (size_t)idx * 8256;
#pragma unroll
        for (int c = 0; c < 8; ++c) {
            __half h = __float2half_rn(st[c]);
            g_hidh[rb + (cq + c) * 256 + j] = __half_as_ushort(h);
            g_hidl[rb + (cq + c) * 256 + j] =
                __half_as_ushort(__float2half_rn(st[c] - __half2float(h)));
        }
    }
#pragma unroll
    for (int c = 0; c < 8; ++c) out_state[b * 8192 + (cq + c) * 256 + j] = st[c];
}

// ---------------- pos_net -> hidden plane cols 8192..8255 ----------------
__global__ void __launch_bounds__(64) posnet_kernel(const int* __restrict__ position,
                                                    const float* __restrict__ wp1,
                                                    const float* __restrict__ bp1,
                                                    const float* __restrict__ wp2,
                                                    const float* __restrict__ bp2) {
    __shared__ float hr[64];
    const int n = blockIdx.x, k = threadIdx.x;
    int p0 = position[n * 2], p1 = position[n * 2 + 1];
    hr[k] = fmaxf(wp1[p0 * 64 + k] + wp1[(16 + p1) * 64 + k] + bp1[k], 0.f);
    __syncthreads();
    float s = bp2[k];
#pragma unroll 8
    for (int j = 0; j < 64; ++j) s += hr[j] * wp2[j * 64 + k];
    __half h = __float2half_rn(s);
    g_hidh[(size_t)n * 8256 + 8192 + k] = __half_as_ushort(h);
    g_hidl[(size_t)n * 8256 + 8192 + k] =
        __half_as_ushort(__float2half_rn(s - __half2float(h)));
}

// ---------------- heads ----------------
__global__ void heads_kernel(const float* __restrict__ wpo2, const float* __restrict__ bpo2,
                             const float* __restrict__ wv2, const float* __restrict__ bv2,
                             float* __restrict__ out_logits, float* __restrict__ out_v) {
    int n = blockIdx.x * blockDim.x + threadIdx.x;
    if (n >= 2048) return;
    const float* z = g_z + (size_t)n * 128;
    float lg[5];
#pragma unroll
    for (int a = 0; a < 5; ++a) lg[a] = bpo2[a];
    float vv = bv2[0];
#pragma unroll 4
    for (int j = 0; j < 64; ++j) {
        float zj = z[j];
#pragma unroll
        for (int a = 0; a < 5; ++a) lg[a] += zj * wpo2[j * 5 + a];
        vv += z[64 + j] * wv2[j];
    }
#pragma unroll
    for (int a = 0; a < 5; ++a) out_logits[n * 5 + a] = lg[a];
    out_v[n] = vv;
}

// ---------------- launch ----------------
extern "C" void kernel_launch(void* const* d_in, const int* in_sizes, int n_in,
                              void* d_out, int out_size) {
    bool dict_order = (in_sizes[3] == 4096 && in_sizes[4] == 6144);
    int wb = dict_order ? 4 : 3;
    int posIdx = dict_order ? 3 : 25;

    const float* image  = (const float*)d_in[0];
    const float* done   = (const float*)d_in[1];
    const float* state0 = (const float*)d_in[2];
    const int*   position = (const int*)d_in[posIdx];
    const float* w1  = (const float*)d_in[wb + 0];
    const float* b1  = (const float*)d_in[wb + 1];
    const float* w2  = (const float*)d_in[wb + 2];
    const float* b2  = (const float*)d_in[wb + 3];
    const float* w3  = (const float*)d_in[wb + 4];
    const float* b3  = (const float*)d_in[wb + 5];
    const float* wfc = (const float*)d_in[wb + 6];
    const float* bfc = (const float*)d_in[wb + 7];
    const float* Ww  = (const float*)d_in[wb + 8];
    const float* bw  = (const float*)d_in[wb + 9];
    const float* wp1 = (const float*)d_in[wb + 10];
    const float* bp1 = (const float*)d_in[wb + 11];
    const float* wp2 = (const float*)d_in[wb + 12];
    const float* bp2 = (const float*)d_in[wb + 13];
    const float* wpo1 = (const float*)d_in[wb + 14];
    const float* bpo1 = (const float*)d_in[wb + 15];
    const float* wpo2 = (const float*)d_in[wb + 16];
    const float* bpo2 = (const float*)d_in[wb + 17];
    const float* wv1 = (const float*)d_in[wb + 18];
    const float* bv1 = (const float*)d_in[wb + 19];
    const float* wv2 = (const float*)d_in[wb + 20];
    const float* bv2 = (const float*)d_in[wb + 21];

    float* out = (float*)d_out;
    float* out_logits = out;
    float* out_v      = out + 10240;
    float* out_state  = out + 12288;

    ush *p_imgh, *p_imgl, *p_a1h, *p_a1l, *p_a2h, *p_a2l, *p_a3h, *p_a3l, *p_hidh, *p_hidl;
    float *p_h, *p_part, *p_z, *p_bcat;
    uint4 *p_w1sw, *p_w2sw, *p_w3sw, *p_wfcsw, *p_wposw;
    cudaGetSymbolAddress((void**)&p_imgh, g_imgh);
    cudaGetSymbolAddress((void**)&p_imgl, g_imgl);
    cudaGetSymbolAddress((void**)&p_a1h, g_a1h);
    cudaGetSymbolAddress((void**)&p_a1l, g_a1l);
    cudaGetSymbolAddress((void**)&p_a2h, g_a2h);
    cudaGetSymbolAddress((void**)&p_a2l, g_a2l);
    cudaGetSymbolAddress((void**)&p_a3h, g_a3h);
    cudaGetSymbolAddress((void**)&p_a3l, g_a3l);
    cudaGetSymbolAddress((void**)&p_hidh, g_hidh);
    cudaGetSymbolAddress((void**)&p_hidl, g_hidl);
    cudaGetSymbolAddress((void**)&p_h, g_h);
    cudaGetSymbolAddress((void**)&p_part, g_part);
    cudaGetSymbolAddress((void**)&p_z, g_z);
    cudaGetSymbolAddress((void**)&p_bcat, g_bcat);
    cudaGetSymbolAddress((void**)&p_w1sw, g_w1sw);
    cudaGetSymbolAddress((void**)&p_w2sw, g_w2sw);
    cudaGetSymbolAddress((void**)&p_w3sw, g_w3sw);
    cudaGetSymbolAddress((void**)&p_wfcsw, g_wfcsw);
    cudaGetSymbolAddress((void**)&p_wposw, g_wposw);

    const int SM64 = 2 * (32768 + 64 * 128);        // 81920
    const int SM1  = 2 * 32768 + 3 * (32 * 128);    // 77824 (conv1: A dbl-buf + resident B)
    cudaFuncSetAttribute(gemmP<3,32>, cudaFuncAttributeMaxDynamicSharedMemorySize, SM1);
    cudaFuncSetAttribute(gemmP<1,64>, cudaFuncAttributeMaxDynamicSharedMemorySize, SM64);
    cudaFuncSetAttribute(gemmP<2,64>, cudaFuncAttributeMaxDynamicSharedMemorySize, SM64);
    cudaFuncSetAttribute(gemmP<0,64>, cudaFuncAttributeMaxDynamicSharedMemorySize, SM64);

    prep_kernel<<<3137, 512>>>(w1, w2, w3, wpo1, wv1, wfc, bpo1, bv1);
    imgprep_kernel<<<56448, 256>>>(image);
    // conv1: M=819200, N=32, K=192 (3 chunks, channel-planar, B-resident)
    gemmP<3,32><<<dim3(1, 6400, 1), 256, SM1>>>(p_imgh, p_imgl, 0, p_w1sw, 3, 3,
                                                (float*)0, p_a1h, p_a1l, 32, 819200, b1, 1);
    // conv2: M=165888, N=64, K=512 (8 chunks)
    gemmP<1,64><<<dim3(1, 1296, 1), 256, SM64>>>(p_a1h, p_a1l, 0, p_w2sw, 8, 8,
                                                 (float*)0, p_a2h, p_a2l, 64, 165888, b2, 1);
    // conv3: M=100352, N=64, K=576 (9 chunks)
    gemmP<2,64><<<dim3(1, 784, 1), 256, SM64>>>(p_a2h, p_a2l, 0, p_w3sw, 9, 9,
                                                (float*)0, p_a3h, p_a3l, 64, 100352, b3, 1);
    // FC: M=2048, N=512 (8 ntiles), K=3136 (49 chunks), split-K=2
    gemmP<0,64><<<dim3(8, 16, 2), 256, SM64>>>(p_a3h, p_a3l, 3136, p_wfcsw, 49, 25,
                                               p_part, (ush*)0, (ush*)0, 512, 2048,
                                               (const float*)0, 0);
    reduce_kernel<<<2048, 512>>>(bfc, p_h, 512, 2, 2048 * 512, 2048 * 512, 1);
    wfeat_kernel<<<256, 256>>>(Ww, bw);
    scan_kernel<<<dim3(64, 4, 1), 256>>>(done, state0, position, out_state);
    posnet_kernel<<<2048, 64>>>(position, wp1, bp1, wp2, bp2);
    // policy/value: M=2048, N=128 (2 ntiles), K=8256 (129 chunks), split-K=8
    gemmP<0,64><<<dim3(2, 16, 8), 256, SM64>>>(p_hidh, p_hidl, 8256, p_wposw, 129, 17,
                                               p_part, (ush*)0, (ush*)0, 128, 2048,
                                               (const float*)0, 0);
    reduce_kernel<<<512, 512>>>(p_bcat, p_z, 128, 8, 2048 * 128, 2048 * 128, 1);
    heads_kernel<<<16, 128>>>(wpo2, bpo2, wv2, bv2, out_logits, out_v);
}